// round 14
// baseline (speedup 1.0000x reference)
#include <cuda_runtime.h>
#include <cuda_bf16.h>
#include <cstdint>

#define NN 100000
#define NE 1000000
#define NG 1000
#define EPSBN 1e-5f
#define NBS 98        // ceil(NN/1024)
#define GB 782        // ceil(NN/128)

// ---------------- static device scratch ----------------
__device__ float g_h[NN * 64];
__device__ float g_res[NN * 64];
__device__ float g_t[NN * 64];
__device__ float g_v[NN * 64];
__device__ float g_scores[NN * 4];
__device__ float g_sums[9 * 128];            // slot 0: feature BN; 1+i: conv i
__device__ __nv_bfloat16 g_wbf[14 * 8192];   // 14 matrices x (hi 4096 + lo 4096), B[n][k]=W[k][n]
__device__ int   g_deg[NN];
__device__ int   g_rowptr[NN + 1];
__device__ int   g_cursor[NN];
__device__ int   g_ssrc[NE];
__device__ int   g_bsum[NBS];
__device__ int   g_gstart[NG + 1];

// ---------------- warp-MMA helpers (sm_80+ PTX, HMMA SASS) ----------------
__device__ __forceinline__ uint32_t smem_u32(const void* p) {
    uint32_t a;
    asm("{ .reg .u64 t; cvta.to.shared.u64 t, %1; cvt.u32.u64 %0, t; }" : "=r"(a) : "l"(p));
    return a;
}

__device__ __forceinline__ void mma_bf16(float* c, const uint32_t* a, const uint32_t* b) {
    asm volatile(
        "mma.sync.aligned.m16n8k16.row.col.f32.bf16.bf16.f32 "
        "{%0,%1,%2,%3}, {%4,%5,%6,%7}, {%8,%9}, {%0,%1,%2,%3};"
        : "+f"(c[0]), "+f"(c[1]), "+f"(c[2]), "+f"(c[3])
        : "r"(a[0]), "r"(a[1]), "r"(a[2]), "r"(a[3]), "r"(b[0]), "r"(b[1]));
}

__device__ __forceinline__ void ldm4(uint32_t* r, uint32_t addr) {
    asm volatile("ldmatrix.sync.aligned.m8n8.x4.shared.b16 {%0,%1,%2,%3}, [%4];"
                 : "=r"(r[0]), "=r"(r[1]), "=r"(r[2]), "=r"(r[3]) : "r"(addr));
}

__device__ __forceinline__ void ldm2(uint32_t* r, uint32_t addr) {
    asm volatile("ldmatrix.sync.aligned.m8n8.x2.shared.b16 {%0,%1}, [%2];"
                 : "=r"(r[0]), "=r"(r[1]) : "r"(addr));
}

__device__ __forceinline__ void hilo2(float f0, float f1, uint32_t& hp, uint32_t& lp) {
    __nv_bfloat162 h = __floats2bfloat162_rn(f0, f1);
    float r0 = f0 - __bfloat162float(__low2bfloat16(h));
    float r1 = f1 - __bfloat162float(__high2bfloat16(h));
    __nv_bfloat162 lo = __floats2bfloat162_rn(r0, r1);
    hp = *(uint32_t*)&h;
    lp = *(uint32_t*)&lo;
}

// ---------------- init ----------------
__global__ void k_init() {
    int i = blockIdx.x * 256 + threadIdx.x;
    if (i < NN) g_deg[i] = 0;
    if (i < 9 * 128) g_sums[i] = 0.f;
}

// ---------------- CSR build (by dst) ----------------
__global__ void k_count(const int* __restrict__ ei) {
    int e = blockIdx.x * 256 + threadIdx.x;
    if (e < NE) atomicAdd(&g_deg[ei[NE + e]], 1);
}

__global__ void k_scan2() {          // single block, 128 threads, shfl scan over NBS
    int tid = threadIdx.x;
    int v = (tid < NBS) ? g_bsum[tid] : 0;
    int orig = v;
#pragma unroll
    for (int o = 1; o < 32; o <<= 1) {
        int u = __shfl_up_sync(0xffffffffu, v, o);
        if ((tid & 31) >= o) v += u;
    }
    __shared__ int wsum[4];
    if ((tid & 31) == 31) wsum[tid >> 5] = v;
    __syncthreads();
    int add = 0;
    for (int w = 0; w < (tid >> 5); w++) add += wsum[w];
    v += add;
    if (tid < NBS) g_bsum[tid] = v - orig;   // exclusive
}

__global__ void k_scan1() {
    __shared__ int s[256];
    int base = blockIdx.x * 1024 + threadIdx.x * 4;
    int sum = 0;
#pragma unroll
    for (int j = 0; j < 4; j++) { int i = base + j; if (i < NN) sum += g_deg[i]; }
    s[threadIdx.x] = sum; __syncthreads();
    for (int off = 128; off > 0; off >>= 1) {
        if (threadIdx.x < off) s[threadIdx.x] += s[threadIdx.x + off];
        __syncthreads();
    }
    if (threadIdx.x == 0) g_bsum[blockIdx.x] = s[0];
}

__global__ void k_scan3() {
    __shared__ int s[256];
    int tid = threadIdx.x;
    int base = blockIdx.x * 1024 + tid * 4;
    int d[4]; int sum = 0;
#pragma unroll
    for (int j = 0; j < 4; j++) { d[j] = (base + j < NN) ? g_deg[base + j] : 0; sum += d[j]; }
    s[tid] = sum; __syncthreads();
    for (int off = 1; off < 256; off <<= 1) {
        int v = 0;
        if (tid >= off) v = s[tid - off];
        __syncthreads();
        if (tid >= off) s[tid] += v;
        __syncthreads();
    }
    int p = g_bsum[blockIdx.x] + s[tid] - sum;
#pragma unroll
    for (int j = 0; j < 4; j++) {
        if (base + j < NN) { g_rowptr[base + j] = p; g_cursor[base + j] = p; }
        p += d[j];
    }
    if (blockIdx.x == 0 && tid == 0) g_rowptr[NN] = NE;
}

__global__ void k_scatter(const int* __restrict__ ei) {
    int e = blockIdx.x * 256 + threadIdx.x;
    if (e < NE) {
        int pos = atomicAdd(&g_cursor[ei[NE + e]], 1);
        g_ssrc[pos] = ei[e];
    }
}

// ---------------- weight prepack: fp32 W[k][n] -> bf16 hi/lo B[n][k] ---------
__global__ void k_prepack(const float* __restrict__ mlpW,
                          const float* __restrict__ projW,
                          const float* __restrict__ Wv) {
    int idx = blockIdx.x * 256 + threadIdx.x;     // 14*4096
    if (idx >= 14 * 4096) return;
    int m = idx >> 12, e = idx & 4095;
    int n = e >> 6, k = e & 63;
    const float* src = (m < 12) ? (mlpW + m * 4096) : ((m == 12) ? projW : Wv);
    float w = src[k * 64 + n];
    __nv_bfloat16 hi = __float2bfloat16_rn(w);
    float lo = w - __bfloat162float(hi);
    g_wbf[m * 8192 + n * 64 + k] = hi;
    g_wbf[m * 8192 + 4096 + n * 64 + k] = __float2bfloat16_rn(lo);
}

// ---------------- feature BN stats over x (slot 0) ----------------
__global__ void k_bnstats(const float* __restrict__ x) {
    __shared__ float ss[256], sq[256];
    int f = threadIdx.x & 63, rq = threadIdx.x >> 6;
    float s = 0.f, q = 0.f;
    for (int r = blockIdx.x * 4 + rq; r < NN; r += gridDim.x * 4) {
        float v = x[r * 64 + f]; s += v; q += v * v;
    }
    ss[threadIdx.x] = s; sq[threadIdx.x] = q; __syncthreads();
    if (threadIdx.x < 64) {
        int t = threadIdx.x;
        atomicAdd(&g_sums[t], ss[t] + ss[t + 64] + ss[t + 128] + ss[t + 192]);
        atomicAdd(&g_sums[64 + t], sq[t] + sq[t + 64] + sq[t + 128] + sq[t + 192]);
    }
}

// ---------------- tensor-core GEMM engine (warp mma, split bf16) ----------------
// CTA = 128 rows x 128 threads. SMEM: A hi/lo 128x64 bf16 swizzled (32KB),
// W hi/lo 64x64 bf16 swizzled (16KB). D = Ahi@Whi + Ahi@Wlo + Alo@Whi.
// Swizzle: 16B chunk c of row r lives at r*128 + ((c ^ (r&7))<<4).

__device__ __forceinline__ void store_A_row(unsigned char* sAhi, unsigned char* sAlo,
                                            int r, const float* d) {
#pragma unroll
    for (int c = 0; c < 8; c++) {
        uint32_t hp[4], lp[4];
#pragma unroll
        for (int q = 0; q < 4; q++)
            hilo2(d[c * 8 + 2 * q], d[c * 8 + 2 * q + 1], hp[q], lp[q]);
        int off = r * 128 + ((c ^ (r & 7)) << 4);
        *(uint4*)(sAhi + off) = make_uint4(hp[0], hp[1], hp[2], hp[3]);
        *(uint4*)(sAlo + off) = make_uint4(lp[0], lp[1], lp[2], lp[3]);
    }
}

__device__ __forceinline__ void load_W(unsigned char* sWhi, unsigned char* sWlo,
                                       int mat, int tid) {
    const uint4* whi = (const uint4*)(g_wbf + mat * 8192);
    const uint4* wlo = (const uint4*)(g_wbf + mat * 8192 + 4096);
#pragma unroll
    for (int i = 0; i < 4; i++) {
        int ch = tid + i * 128;          // 0..511
        int n = ch >> 3, c = ch & 7;
        int off = n * 128 + ((c ^ (n & 7)) << 4);
        *(uint4*)(sWhi + off) = __ldg(&whi[ch]);
        *(uint4*)(sWlo + off) = __ldg(&wlo[ch]);
    }
}

// mode: 0=proj (BN pre from slot0, relu, store g_h+g_res)
//       1=mlp3 (fused CSR gather of g_h -> 3-layer MLP -> g_t + BN stats to slot)
//       2=v    (g_h -> g_v, + fused attention scores from Wk/seed)
__global__ void __launch_bounds__(128) k_tc(int mode, int nlayers,
                                            const float* __restrict__ xin,
                                            int mat,
                                            const float* __restrict__ bias,
                                            int slot,
                                            const float* __restrict__ aux0,
                                            const float* __restrict__ aux1) {
    __shared__ __align__(16) unsigned char smem[49152];
    unsigned char* sAhi = smem;
    unsigned char* sAlo = smem + 16384;
    unsigned char* sWhi = smem + 32768;
    unsigned char* sWlo = smem + 40960;
    float* sstats = (float*)(smem + 32768);   // overlay: BN stats after final mma
    float* saux   = (float*)(smem + 32768);   // overlay: scale/shift or score weights (prologue)

    int tid = threadIdx.x;
    int w = tid >> 5, lane = tid & 31;
    int gid = lane >> 2, tid4 = lane & 3;
    int blockbase = blockIdx.x * 128;
    int row = blockbase + tid;
    bool valid = row < NN;

    uint32_t sAhi_a = smem_u32(sAhi), sAlo_a = smem_u32(sAlo);
    uint32_t sWhi_a = smem_u32(sWhi), sWlo_a = smem_u32(sWlo);

    // ---- prologue: build A tile ----
    if (mode == 1) {
        // fused gather: t[n] = h[n] + sum_{src in N(n)} h[src], straight into sA
        // 8 groups of 16 lanes; each iteration fills 8 rows; 16 iterations -> 128 rows
        const float4* h4 = (const float4*)g_h;
        int grp = tid >> 4, lane16 = tid & 15;
#pragma unroll 1
        for (int p = 0; p < 16; p++) {
            int r = p * 8 + grp;
            int rr = blockbase + r;
            float4 acc = make_float4(0.f, 0.f, 0.f, 0.f);
            if (rr < NN) {
                acc = h4[rr * 16 + lane16];
                int e = g_rowptr[rr], e1 = g_rowptr[rr + 1];
                for (; e + 1 < e1; e += 2) {
                    int s0 = __ldg(&g_ssrc[e]), s1 = __ldg(&g_ssrc[e + 1]);
                    float4 b0 = h4[s0 * 16 + lane16];
                    float4 b1 = h4[s1 * 16 + lane16];
                    acc.x += b0.x + b1.x; acc.y += b0.y + b1.y;
                    acc.z += b0.z + b1.z; acc.w += b0.w + b1.w;
                }
                if (e < e1) {
                    int s0 = __ldg(&g_ssrc[e]);
                    float4 b0 = h4[s0 * 16 + lane16];
                    acc.x += b0.x; acc.y += b0.y; acc.z += b0.z; acc.w += b0.w;
                }
            }
            uint32_t hp0, lp0, hp1, lp1;
            hilo2(acc.x, acc.y, hp0, lp0);
            hilo2(acc.z, acc.w, hp1, lp1);
            int c = lane16 >> 1;
            int off = r * 128 + ((c ^ (r & 7)) << 4) + ((lane16 & 1) << 3);
            *(uint2*)(sAhi + off) = make_uint2(hp0, hp1);
            *(uint2*)(sAlo + off) = make_uint2(lp0, lp1);
        }
        load_W(sWhi, sWlo, mat, tid);
        __syncthreads();
    } else {
        // aux compute in sW overlay (free until load_W)
        if (mode == 0) {
            if (tid < 64) {
                float mean = g_sums[tid] * (1.f / NN);
                float var = fmaxf(g_sums[64 + tid] * (1.f / NN) - mean * mean, 0.f);
                float sc = aux0[tid] * rsqrtf(var + EPSBN);   // aux0=fn_gamma
                saux[tid] = sc;
                saux[64 + tid] = aux1[tid] - mean * sc;       // aux1=fn_beta
            }
        } else { // mode 2: score weights ws[h*64+j] = 0.25 * Wk[:,h*16+d] . seed[h][d]
            for (int e = tid; e < 256; e += 128) {
                int j = e >> 2, h = e & 3;
                float s = 0.f;
#pragma unroll
                for (int dd = 0; dd < 16; dd++)
                    s += aux0[j * 64 + h * 16 + dd] * aux1[h * 16 + dd];  // aux0=Wk, aux1=seed
                saux[h * 64 + j] = s * 0.25f;
            }
        }
        const float* src = (mode == 2) ? g_h : xin;
        float d[64];
        const float4* in4 = (const float4*)src;
#pragma unroll
        for (int i = 0; i < 16; i++) {
            float4 v = valid ? in4[row * 16 + i] : make_float4(0.f, 0.f, 0.f, 0.f);
            d[4 * i] = v.x; d[4 * i + 1] = v.y; d[4 * i + 2] = v.z; d[4 * i + 3] = v.w;
        }
        __syncthreads();   // saux ready
        if (mode == 0) {
#pragma unroll
            for (int j = 0; j < 64; j++) d[j] = d[j] * saux[j] + saux[64 + j];
        } else if (valid) {
            float s0 = 0.f, s1 = 0.f, s2 = 0.f, s3 = 0.f;
#pragma unroll
            for (int j = 0; j < 64; j++) {
                float a = d[j];
                s0 += a * saux[j];       s1 += a * saux[64 + j];
                s2 += a * saux[128 + j]; s3 += a * saux[192 + j];
            }
            ((float4*)g_scores)[row] = make_float4(s0, s1, s2, s3);
        }
        store_A_row(sAhi, sAlo, tid, d);
        __syncthreads();   // all saux reads done before load_W overwrites
        load_W(sWhi, sWlo, mat, tid);
        __syncthreads();
    }

    // ---- layer loop ----
    float acc[2][8][4];
    for (int l = 0; l < nlayers; l++) {
#pragma unroll
        for (int rt = 0; rt < 2; rt++)
#pragma unroll
            for (int n = 0; n < 8; n++)
#pragma unroll
                for (int q = 0; q < 4; q++) acc[rt][n][q] = 0.f;

#pragma unroll
        for (int seg = 0; seg < 3; seg++) {
            uint32_t Aa = (seg < 2) ? sAhi_a : sAlo_a;
            uint32_t Ba = (seg == 1) ? sWlo_a : sWhi_a;
#pragma unroll
            for (int ks = 0; ks < 4; ks++) {
                uint32_t a[2][4];
#pragma unroll
                for (int rt = 0; rt < 2; rt++) {
                    int r = w * 32 + rt * 16 + (lane & 15);
                    int ch = 2 * ks + (lane >> 4);
                    ldm4(a[rt], Aa + r * 128 + ((ch ^ (r & 7)) << 4));
                }
#pragma unroll
                for (int n = 0; n < 8; n++) {
                    int nr = n * 8 + (lane & 7);
                    int ch = 2 * ks + ((lane >> 3) & 1);
                    uint32_t b[2];
                    ldm2(b, Ba + nr * 128 + ((ch ^ (nr & 7)) << 4));
                    mma_bf16(acc[0][n], a[0], b);
                    mma_bf16(acc[1][n], a[1], b);
                }
            }
        }

        if (bias) {
            const float* bl = bias + l * 64;
#pragma unroll
            for (int n = 0; n < 8; n++) {
                float2 bb = __ldg((const float2*)(bl + n * 8 + 2 * tid4));
#pragma unroll
                for (int rt = 0; rt < 2; rt++) {
                    acc[rt][n][0] += bb.x; acc[rt][n][1] += bb.y;
                    acc[rt][n][2] += bb.x; acc[rt][n][3] += bb.y;
                }
            }
        }

        if (l < nlayers - 1) {
            __syncthreads();
#pragma unroll
            for (int rt = 0; rt < 2; rt++)
#pragma unroll
                for (int rr = 0; rr < 2; rr++) {
                    int r = w * 32 + rt * 16 + rr * 8 + gid;
#pragma unroll
                    for (int n = 0; n < 8; n++) {
                        float f0 = fmaxf(acc[rt][n][2 * rr], 0.f);
                        float f1 = fmaxf(acc[rt][n][2 * rr + 1], 0.f);
                        uint32_t hp, lp;
                        hilo2(f0, f1, hp, lp);
                        int off = r * 128 + ((n ^ (r & 7)) << 4) + 4 * tid4;
                        *(uint32_t*)(sAhi + off) = hp;
                        *(uint32_t*)(sAlo + off) = lp;
                    }
                }
            load_W(sWhi, sWlo, mat + l + 1, tid);
            __syncthreads();
        }
    }

    // ---- epilogue (fragment layout) ----
    if (mode == 1) {
#pragma unroll
        for (int rt = 0; rt < 2; rt++)
#pragma unroll
            for (int rr = 0; rr < 2; rr++) {
                int r = blockbase + w * 32 + rt * 16 + rr * 8 + gid;
                if (r < NN) {
#pragma unroll
                    for (int n = 0; n < 8; n++)
                        *(float2*)(g_t + r * 64 + n * 8 + 2 * tid4) =
                            make_float2(acc[rt][n][2 * rr], acc[rt][n][2 * rr + 1]);
                }
            }
        // BN stats on z (masked)
        float s[16], q[16];
#pragma unroll
        for (int n = 0; n < 8; n++)
#pragma unroll
            for (int h = 0; h < 2; h++) {
                float as = 0.f, aq = 0.f;
#pragma unroll
                for (int rt = 0; rt < 2; rt++)
#pragma unroll
                    for (int rr = 0; rr < 2; rr++) {
                        int r = blockbase + w * 32 + rt * 16 + rr * 8 + gid;
                        if (r < NN) {
                            float z = acc[rt][n][2 * rr + h];
                            as += z; aq += z * z;
                        }
                    }
                s[n * 2 + h] = as; q[n * 2 + h] = aq;
            }
#pragma unroll
        for (int idx = 0; idx < 16; idx++)
#pragma unroll
            for (int o = 4; o < 32; o <<= 1) {
                s[idx] += __shfl_xor_sync(0xffffffffu, s[idx], o);
                q[idx] += __shfl_xor_sync(0xffffffffu, q[idx], o);
            }
        __syncthreads();           // mma reads of sW done -> overlay
        sstats[tid] = 0.f;
        __syncthreads();
        if (gid == 0) {
#pragma unroll
            for (int n = 0; n < 8; n++)
#pragma unroll
                for (int h = 0; h < 2; h++) {
                    int col = n * 8 + 2 * tid4 + h;
                    atomicAdd(&sstats[col], s[n * 2 + h]);
                    atomicAdd(&sstats[64 + col], q[n * 2 + h]);
                }
        }
        __syncthreads();
        atomicAdd(&g_sums[slot * 128 + tid], sstats[tid]);
    } else {
        float* dst = (mode == 0) ? g_h : g_v;
#pragma unroll
        for (int rt = 0; rt < 2; rt++)
#pragma unroll
            for (int rr = 0; rr < 2; rr++) {
                int r = blockbase + w * 32 + rt * 16 + rr * 8 + gid;
                if (r < NN) {
#pragma unroll
                    for (int n = 0; n < 8; n++) {
                        float f0 = acc[rt][n][2 * rr], f1 = acc[rt][n][2 * rr + 1];
                        if (mode == 0) { f0 = fmaxf(f0, 0.f); f1 = fmaxf(f1, 0.f); }
                        *(float2*)(dst + r * 64 + n * 8 + 2 * tid4) = make_float2(f0, f1);
                        if (mode == 0)
                            *(float2*)(g_res + r * 64 + n * 8 + 2 * tid4) = make_float2(f0, f1);
                    }
                }
            }
    }
}

// ---------------- BN finalize + apply + relu (+ residual) --------------------
__global__ void k_apply(int addres, int slot,
                        const float* __restrict__ gamma,
                        const float* __restrict__ beta) {
    __shared__ float ssc[64], ssh[64];
    int tid = threadIdx.x;
    if (tid < 64) {
        float mean = g_sums[slot * 128 + tid] * (1.f / NN);
        float var = fmaxf(g_sums[slot * 128 + 64 + tid] * (1.f / NN) - mean * mean, 0.f);
        float sc = gamma[tid] * rsqrtf(var + EPSBN);
        ssc[tid] = sc;
        ssh[tid] = beta[tid] - mean * sc;
    }
    __syncthreads();
    int i = blockIdx.x * 256 + tid;   // float4 index, exactly NN*16
    int f4 = i & 15;
    float4 sc = ((const float4*)ssc)[f4];
    float4 sh = ((const float4*)ssh)[f4];
    float4 z = ((const float4*)g_t)[i];
    float4 v;
    v.x = fmaxf(z.x * sc.x + sh.x, 0.f);
    v.y = fmaxf(z.y * sc.y + sh.y, 0.f);
    v.z = fmaxf(z.z * sc.z + sh.z, 0.f);
    v.w = fmaxf(z.w * sc.w + sh.w, 0.f);
    if (addres) {
        float4 r = ((const float4*)g_res)[i];
        v.x += r.x; v.y += r.y; v.z += r.z; v.w += r.w;
        ((float4*)g_res)[i] = v;
    }
    ((float4*)g_h)[i] = v;
}

// ---------------- readout ----------------
__global__ void k_bounds(const int* __restrict__ batch) {
    int i = blockIdx.x * 256 + threadIdx.x;
    if (i >= NN) return;
    int b = batch[i];
    int bp = (i == 0) ? -1 : batch[i - 1];
    for (int g = bp + 1; g <= b; g++) g_gstart[g] = i;
    if (i == NN - 1) {
        for (int g = b + 1; g <= NG; g++) g_gstart[g] = NN;
    }
}

__global__ void __launch_bounds__(128) k_readout(const float* __restrict__ Wo,
                                                 const float* __restrict__ predW,
                                                 const float* __restrict__ predb,
                                                 float* __restrict__ out) {
    int g = blockIdx.x, tid = threadIdx.x;
    int s = g_gstart[g], e = g_gstart[g + 1];
    __shared__ float smw[4 * 68];
    __shared__ float red[68];
    __shared__ float pn[64];
    __shared__ float emb[64];
    __shared__ float wmx[4][4];
    const float4* sc4 = (const float4*)g_scores;

    float m[4] = {-1e30f, -1e30f, -1e30f, -1e30f};
    for (int n = s + tid; n < e; n += 128) {
        float4 v = sc4[n];
        m[0] = fmaxf(m[0], v.x); m[1] = fmaxf(m[1], v.y);
        m[2] = fmaxf(m[2], v.z); m[3] = fmaxf(m[3], v.w);
    }
#pragma unroll
    for (int h = 0; h < 4; h++)
#pragma unroll
        for (int d = 16; d; d >>= 1)
            m[h] = fmaxf(m[h], __shfl_xor_sync(0xffffffffu, m[h], d));
    if ((tid & 31) == 0)
#pragma unroll
        for (int h = 0; h < 4; h++) wmx[tid >> 5][h] = m[h];
    __syncthreads();
#pragma unroll
    for (int h = 0; h < 4; h++)
        m[h] = fmaxf(fmaxf(wmx[0][h], wmx[1][h]), fmaxf(wmx[2][h], wmx[3][h]));

    float pool[64];
    float sw[4] = {0.f, 0.f, 0.f, 0.f};
#pragma unroll
    for (int k = 0; k < 64; k++) pool[k] = 0.f;
    for (int n = s + tid; n < e; n += 128) {
        float4 v = sc4[n];
        float w[4] = {expf(v.x - m[0]), expf(v.y - m[1]),
                      expf(v.z - m[2]), expf(v.w - m[3])};
        sw[0] += w[0]; sw[1] += w[1]; sw[2] += w[2]; sw[3] += w[3];
        const float4* vv = (const float4*)(g_v + n * 64);
#pragma unroll
        for (int h = 0; h < 4; h++) {
#pragma unroll
            for (int i = 0; i < 4; i++) {
                float4 t = vv[h * 4 + i];
                pool[h * 16 + i * 4 + 0] += w[h] * t.x;
                pool[h * 16 + i * 4 + 1] += w[h] * t.y;
                pool[h * 16 + i * 4 + 2] += w[h] * t.z;
                pool[h * 16 + i * 4 + 3] += w[h] * t.w;
            }
        }
    }
#pragma unroll
    for (int k = 0; k < 64; k++)
#pragma unroll
        for (int d = 16; d; d >>= 1)
            pool[k] += __shfl_xor_sync(0xffffffffu, pool[k], d);
#pragma unroll
    for (int h = 0; h < 4; h++)
#pragma unroll
        for (int d = 16; d; d >>= 1)
            sw[h] += __shfl_xor_sync(0xffffffffu, sw[h], d);
    int wid = tid >> 5;
    if ((tid & 31) == 0) {
#pragma unroll
        for (int k = 0; k < 64; k++) smw[wid * 68 + k] = pool[k];
#pragma unroll
        for (int h = 0; h < 4; h++) smw[wid * 68 + 64 + h] = sw[h];
    }
    __syncthreads();
    if (tid < 68) red[tid] = smw[tid] + smw[68 + tid] + smw[136 + tid] + smw[204 + tid];
    __syncthreads();
    if (tid < 64) {
        float den = red[64 + (tid >> 4)];
        pn[tid] = (den > 0.f) ? red[tid] / den : 0.f;
    }
    __syncthreads();
    if (tid < 64) {
        float s2 = 0.f;
        for (int k = 0; k < 64; k++) s2 += pn[k] * Wo[k * 64 + tid];
        emb[tid] = s2;
        out[g * 64 + tid] = s2;
    }
    __syncthreads();
    {
        float s2 = predb[tid];
        for (int k = 0; k < 64; k++) s2 += emb[k] * predW[k * 128 + tid];
        out[NG * 64 + g * 128 + tid] = s2;
    }
}

// ---------------- launch ----------------
extern "C" void kernel_launch(void* const* d_in, const int* in_sizes, int n_in,
                              void* d_out, int out_size) {
    const float* x        = (const float*)d_in[0];
    const int*   ei       = (const int*)d_in[1];
    const int*   batch    = (const int*)d_in[2];
    const float* fn_gamma = (const float*)d_in[3];
    const float* fn_beta  = (const float*)d_in[4];
    const float* proj_W   = (const float*)d_in[5];
    const float* proj_b   = (const float*)d_in[6];
    const float* mlp_W    = (const float*)d_in[7];
    const float* mlp_b    = (const float*)d_in[8];
    const float* norm_g   = (const float*)d_in[9];
    const float* norm_b   = (const float*)d_in[10];
    const float* seed     = (const float*)d_in[11];
    const float* Wk       = (const float*)d_in[12];
    const float* Wv       = (const float*)d_in[13];
    const float* Wo       = (const float*)d_in[14];
    const float* predW    = (const float*)d_in[15];
    const float* predb    = (const float*)d_in[16];
    float* out = (float*)d_out;

    k_init<<<391, 256>>>();
    k_count<<<3907, 256>>>(ei);
    k_scan1<<<NBS, 256>>>();
    k_scan2<<<1, 128>>>();
    k_scan3<<<NBS, 256>>>();
    k_scatter<<<3907, 256>>>(ei);

    k_prepack<<<224, 256>>>(mlp_W, proj_W, Wv);
    k_bnstats<<<512, 256>>>(x);
    k_tc<<<GB, 128>>>(0, 1, x, 12, proj_b, 0, fn_gamma, fn_beta);   // BN+proj

    for (int m = 0; m < 4; m++) {
        for (int c = 0; c < 2; c++) {
            int slot = 1 + m * 2 + c;
            k_tc<<<GB, 128>>>(1, 3, nullptr, m * 3, mlp_b + m * 192, slot, nullptr, nullptr);
            k_apply<<<6250, 256>>>(c, slot, norm_g + m * 64, norm_b + m * 64);
        }
    }

    k_tc<<<GB, 128>>>(2, 1, nullptr, 13, nullptr, 0, Wk, seed);     // v + fused scores
    k_bounds<<<391, 256>>>(batch);
    k_readout<<<NG, 128>>>(Wo, predW, predb, out);
}

// round 15
// speedup vs baseline: 1.4704x; 1.4704x over previous
#include <cuda_runtime.h>
#include <cuda_bf16.h>
#include <cstdint>

#define NN 100000
#define NE 1000000
#define NG 1000
#define EPSBN 1e-5f
#define NBS 98        // ceil(NN/1024)
#define GB 782        // ceil(NN/128)

// ---------------- static device scratch ----------------
__device__ float g_h[NN * 64];
__device__ float g_res[NN * 64];
__device__ float g_t[NN * 64];
__device__ float g_v[NN * 64];
__device__ float g_scores[NN * 4];
__device__ float g_sums[9 * 128];            // slot 0: feature BN; 1+i: conv i
__device__ __nv_bfloat16 g_wbf[14 * 8192];   // 14 matrices x (hi 4096 + lo 4096), B[n][k]=W[k][n]
__device__ int   g_deg[NN];
__device__ int   g_rowptr[NN + 1];
__device__ int   g_cursor[NN];
__device__ int   g_ssrc[NE];
__device__ int   g_bsum[NBS];
__device__ int   g_gstart[NG + 1];

// ---------------- warp-MMA helpers (sm_80+ PTX, HMMA SASS) ----------------
__device__ __forceinline__ uint32_t smem_u32(const void* p) {
    uint32_t a;
    asm("{ .reg .u64 t; cvta.to.shared.u64 t, %1; cvt.u32.u64 %0, t; }" : "=r"(a) : "l"(p));
    return a;
}

__device__ __forceinline__ void mma_bf16(float* c, const uint32_t* a, const uint32_t* b) {
    asm volatile(
        "mma.sync.aligned.m16n8k16.row.col.f32.bf16.bf16.f32 "
        "{%0,%1,%2,%3}, {%4,%5,%6,%7}, {%8,%9}, {%0,%1,%2,%3};"
        : "+f"(c[0]), "+f"(c[1]), "+f"(c[2]), "+f"(c[3])
        : "r"(a[0]), "r"(a[1]), "r"(a[2]), "r"(a[3]), "r"(b[0]), "r"(b[1]));
}

__device__ __forceinline__ void ldm4(uint32_t* r, uint32_t addr) {
    asm volatile("ldmatrix.sync.aligned.m8n8.x4.shared.b16 {%0,%1,%2,%3}, [%4];"
                 : "=r"(r[0]), "=r"(r[1]), "=r"(r[2]), "=r"(r[3]) : "r"(addr));
}

__device__ __forceinline__ void ldm2(uint32_t* r, uint32_t addr) {
    asm volatile("ldmatrix.sync.aligned.m8n8.x2.shared.b16 {%0,%1}, [%2];"
                 : "=r"(r[0]), "=r"(r[1]) : "r"(addr));
}

__device__ __forceinline__ void hilo2(float f0, float f1, uint32_t& hp, uint32_t& lp) {
    __nv_bfloat162 h = __floats2bfloat162_rn(f0, f1);
    float r0 = f0 - __bfloat162float(__low2bfloat16(h));
    float r1 = f1 - __bfloat162float(__high2bfloat16(h));
    __nv_bfloat162 lo = __floats2bfloat162_rn(r0, r1);
    hp = *(uint32_t*)&h;
    lp = *(uint32_t*)&lo;
}

// ---------------- init ----------------
__global__ void k_init() {
    int i = blockIdx.x * 256 + threadIdx.x;
    if (i < NN) g_deg[i] = 0;
    if (i < 9 * 128) g_sums[i] = 0.f;
}

// ---------------- CSR build (by dst) ----------------
__global__ void k_count(const int* __restrict__ ei) {
    int e = blockIdx.x * 256 + threadIdx.x;
    if (e < NE) atomicAdd(&g_deg[ei[NE + e]], 1);
}

__global__ void k_scan1() {
    __shared__ int s[256];
    int base = blockIdx.x * 1024 + threadIdx.x * 4;
    int sum = 0;
#pragma unroll
    for (int j = 0; j < 4; j++) { int i = base + j; if (i < NN) sum += g_deg[i]; }
    s[threadIdx.x] = sum; __syncthreads();
    for (int off = 128; off > 0; off >>= 1) {
        if (threadIdx.x < off) s[threadIdx.x] += s[threadIdx.x + off];
        __syncthreads();
    }
    if (threadIdx.x == 0) g_bsum[blockIdx.x] = s[0];
}

__global__ void k_scan2() {          // single block, 128 threads, shfl scan over NBS
    int tid = threadIdx.x;
    int v = (tid < NBS) ? g_bsum[tid] : 0;
    int orig = v;
#pragma unroll
    for (int o = 1; o < 32; o <<= 1) {
        int u = __shfl_up_sync(0xffffffffu, v, o);
        if ((tid & 31) >= o) v += u;
    }
    __shared__ int wsum[4];
    if ((tid & 31) == 31) wsum[tid >> 5] = v;
    __syncthreads();
    int add = 0;
    for (int w = 0; w < (tid >> 5); w++) add += wsum[w];
    v += add;
    if (tid < NBS) g_bsum[tid] = v - orig;   // exclusive
}

__global__ void k_scan3() {
    __shared__ int s[256];
    int tid = threadIdx.x;
    int base = blockIdx.x * 1024 + tid * 4;
    int d[4]; int sum = 0;
#pragma unroll
    for (int j = 0; j < 4; j++) { d[j] = (base + j < NN) ? g_deg[base + j] : 0; sum += d[j]; }
    s[tid] = sum; __syncthreads();
    for (int off = 1; off < 256; off <<= 1) {
        int v = 0;
        if (tid >= off) v = s[tid - off];
        __syncthreads();
        if (tid >= off) s[tid] += v;
        __syncthreads();
    }
    int p = g_bsum[blockIdx.x] + s[tid] - sum;
#pragma unroll
    for (int j = 0; j < 4; j++) {
        if (base + j < NN) { g_rowptr[base + j] = p; g_cursor[base + j] = p; }
        p += d[j];
    }
    if (blockIdx.x == 0 && tid == 0) g_rowptr[NN] = NE;
}

__global__ void k_scatter(const int* __restrict__ ei) {
    int e = blockIdx.x * 256 + threadIdx.x;
    if (e < NE) {
        int pos = atomicAdd(&g_cursor[ei[NE + e]], 1);
        g_ssrc[pos] = ei[e];
    }
}

// ---------------- weight prepack: fp32 W[k][n] -> bf16 hi/lo B[n][k] ---------
__global__ void k_prepack(const float* __restrict__ mlpW,
                          const float* __restrict__ projW,
                          const float* __restrict__ Wv) {
    int idx = blockIdx.x * 256 + threadIdx.x;     // 14*4096
    if (idx >= 14 * 4096) return;
    int m = idx >> 12, e = idx & 4095;
    int n = e >> 6, k = e & 63;
    const float* src = (m < 12) ? (mlpW + m * 4096) : ((m == 12) ? projW : Wv);
    float w = src[k * 64 + n];
    __nv_bfloat16 hi = __float2bfloat16_rn(w);
    float lo = w - __bfloat162float(hi);
    g_wbf[m * 8192 + n * 64 + k] = hi;
    g_wbf[m * 8192 + 4096 + n * 64 + k] = __float2bfloat16_rn(lo);
}

// ---------------- feature BN stats over x (slot 0) ----------------
__global__ void k_bnstats(const float* __restrict__ x) {
    __shared__ float ss[256], sq[256];
    int f = threadIdx.x & 63, rq = threadIdx.x >> 6;
    float s = 0.f, q = 0.f;
    for (int r = blockIdx.x * 4 + rq; r < NN; r += gridDim.x * 4) {
        float v = x[r * 64 + f]; s += v; q += v * v;
    }
    ss[threadIdx.x] = s; sq[threadIdx.x] = q; __syncthreads();
    if (threadIdx.x < 64) {
        int t = threadIdx.x;
        atomicAdd(&g_sums[t], ss[t] + ss[t + 64] + ss[t + 128] + ss[t + 192]);
        atomicAdd(&g_sums[64 + t], sq[t] + sq[t + 64] + sq[t + 128] + sq[t + 192]);
    }
}

// ---------------- tensor-core GEMM engine (warp mma, split bf16) ----------------
// CTA = 128 rows x 128 threads. SMEM: A hi/lo 128x64 bf16 swizzled (32KB),
// W hi/lo 64x64 bf16 swizzled (16KB). D = Ahi@Whi + Ahi@Wlo + Alo@Whi.
// Swizzle: 16B chunk c of row r lives at r*128 + ((c ^ (r&7))<<4).

__device__ __forceinline__ void store_A_row(unsigned char* sAhi, unsigned char* sAlo,
                                            int r, const float* d) {
#pragma unroll
    for (int c = 0; c < 8; c++) {
        uint32_t hp[4], lp[4];
#pragma unroll
        for (int q = 0; q < 4; q++)
            hilo2(d[c * 8 + 2 * q], d[c * 8 + 2 * q + 1], hp[q], lp[q]);
        int off = r * 128 + ((c ^ (r & 7)) << 4);
        *(uint4*)(sAhi + off) = make_uint4(hp[0], hp[1], hp[2], hp[3]);
        *(uint4*)(sAlo + off) = make_uint4(lp[0], lp[1], lp[2], lp[3]);
    }
}

__device__ __forceinline__ void load_W(unsigned char* sWhi, unsigned char* sWlo,
                                       int mat, int tid) {
    const uint4* whi = (const uint4*)(g_wbf + mat * 8192);
    const uint4* wlo = (const uint4*)(g_wbf + mat * 8192 + 4096);
#pragma unroll
    for (int i = 0; i < 4; i++) {
        int ch = tid + i * 128;          // 0..511
        int n = ch >> 3, c = ch & 7;
        int off = n * 128 + ((c ^ (n & 7)) << 4);
        *(uint4*)(sWhi + off) = __ldg(&whi[ch]);
        *(uint4*)(sWlo + off) = __ldg(&wlo[ch]);
    }
}

// mode: 0=proj (BN pre from slot0, relu, store g_h+g_res)
//       1=mlp3 (g_t -> 3-layer MLP -> g_t + BN stats to slot)
//       2=v    (g_h -> g_v, + fused attention scores from Wk/seed)
__global__ void __launch_bounds__(128) k_tc(int mode, int nlayers,
                                            const float* __restrict__ xin,
                                            int mat,
                                            const float* __restrict__ bias,
                                            int slot,
                                            const float* __restrict__ aux0,
                                            const float* __restrict__ aux1) {
    __shared__ __align__(16) unsigned char smem[49152];
    unsigned char* sAhi = smem;
    unsigned char* sAlo = smem + 16384;
    unsigned char* sWhi = smem + 32768;
    unsigned char* sWlo = smem + 40960;
    float* sstats = (float*)(smem + 32768);   // overlay: BN stats after final mma
    float* saux   = (float*)(smem + 32768);   // overlay: scale/shift or score weights (prologue)

    int tid = threadIdx.x;
    int w = tid >> 5, lane = tid & 31;
    int gid = lane >> 2, tid4 = lane & 3;
    int blockbase = blockIdx.x * 128;
    int row = blockbase + tid;
    bool valid = row < NN;

    uint32_t sAhi_a = smem_u32(sAhi), sAlo_a = smem_u32(sAlo);
    uint32_t sWhi_a = smem_u32(sWhi), sWlo_a = smem_u32(sWlo);

    // ---- prologue: build A tile ----
    // aux compute in sW overlay (free until load_W)
    if (mode == 0) {
        if (tid < 64) {
            float mean = g_sums[tid] * (1.f / NN);
            float var = fmaxf(g_sums[64 + tid] * (1.f / NN) - mean * mean, 0.f);
            float sc = aux0[tid] * rsqrtf(var + EPSBN);   // aux0=fn_gamma
            saux[tid] = sc;
            saux[64 + tid] = aux1[tid] - mean * sc;       // aux1=fn_beta
        }
    } else if (mode == 2) { // score weights ws[h*64+j] = 0.25 * Wk[:,h*16+d] . seed[h][d]
        for (int e = tid; e < 256; e += 128) {
            int j = e >> 2, h = e & 3;
            float s = 0.f;
#pragma unroll
            for (int dd = 0; dd < 16; dd++)
                s += aux0[j * 64 + h * 16 + dd] * aux1[h * 16 + dd];  // aux0=Wk, aux1=seed
            saux[h * 64 + j] = s * 0.25f;
        }
    }
    {
        const float* src = (mode == 1) ? g_t : ((mode == 2) ? g_h : xin);
        float d[64];
        const float4* in4 = (const float4*)src;
#pragma unroll
        for (int i = 0; i < 16; i++) {
            float4 v = valid ? in4[row * 16 + i] : make_float4(0.f, 0.f, 0.f, 0.f);
            d[4 * i] = v.x; d[4 * i + 1] = v.y; d[4 * i + 2] = v.z; d[4 * i + 3] = v.w;
        }
        if (mode != 1) __syncthreads();   // saux ready
        if (mode == 0) {
#pragma unroll
            for (int j = 0; j < 64; j++) d[j] = d[j] * saux[j] + saux[64 + j];
        } else if (mode == 2 && valid) {
            float s0 = 0.f, s1 = 0.f, s2 = 0.f, s3 = 0.f;
#pragma unroll
            for (int j = 0; j < 64; j++) {
                float a = d[j];
                s0 += a * saux[j];       s1 += a * saux[64 + j];
                s2 += a * saux[128 + j]; s3 += a * saux[192 + j];
            }
            ((float4*)g_scores)[row] = make_float4(s0, s1, s2, s3);
        }
        store_A_row(sAhi, sAlo, tid, d);
        if (mode != 1) __syncthreads();   // all saux reads done before load_W overwrites
        load_W(sWhi, sWlo, mat, tid);
        __syncthreads();
    }

    // ---- layer loop ----
    float acc[2][8][4];
    for (int l = 0; l < nlayers; l++) {
#pragma unroll
        for (int rt = 0; rt < 2; rt++)
#pragma unroll
            for (int n = 0; n < 8; n++)
#pragma unroll
                for (int q = 0; q < 4; q++) acc[rt][n][q] = 0.f;

#pragma unroll
        for (int seg = 0; seg < 3; seg++) {
            uint32_t Aa = (seg < 2) ? sAhi_a : sAlo_a;
            uint32_t Ba = (seg == 1) ? sWlo_a : sWhi_a;
#pragma unroll
            for (int ks = 0; ks < 4; ks++) {
                uint32_t a[2][4];
#pragma unroll
                for (int rt = 0; rt < 2; rt++) {
                    int r = w * 32 + rt * 16 + (lane & 15);
                    int ch = 2 * ks + (lane >> 4);
                    ldm4(a[rt], Aa + r * 128 + ((ch ^ (r & 7)) << 4));
                }
#pragma unroll
                for (int n = 0; n < 8; n++) {
                    int nr = n * 8 + (lane & 7);
                    int ch = 2 * ks + ((lane >> 3) & 1);
                    uint32_t b[2];
                    ldm2(b, Ba + nr * 128 + ((ch ^ (nr & 7)) << 4));
                    mma_bf16(acc[0][n], a[0], b);
                    mma_bf16(acc[1][n], a[1], b);
                }
            }
        }

        if (bias) {
            const float* bl = bias + l * 64;
#pragma unroll
            for (int n = 0; n < 8; n++) {
                float2 bb = __ldg((const float2*)(bl + n * 8 + 2 * tid4));
#pragma unroll
                for (int rt = 0; rt < 2; rt++) {
                    acc[rt][n][0] += bb.x; acc[rt][n][1] += bb.y;
                    acc[rt][n][2] += bb.x; acc[rt][n][3] += bb.y;
                }
            }
        }

        if (l < nlayers - 1) {
            __syncthreads();
#pragma unroll
            for (int rt = 0; rt < 2; rt++)
#pragma unroll
                for (int rr = 0; rr < 2; rr++) {
                    int r = w * 32 + rt * 16 + rr * 8 + gid;
#pragma unroll
                    for (int n = 0; n < 8; n++) {
                        float f0 = fmaxf(acc[rt][n][2 * rr], 0.f);
                        float f1 = fmaxf(acc[rt][n][2 * rr + 1], 0.f);
                        uint32_t hp, lp;
                        hilo2(f0, f1, hp, lp);
                        int off = r * 128 + ((n ^ (r & 7)) << 4) + 4 * tid4;
                        *(uint32_t*)(sAhi + off) = hp;
                        *(uint32_t*)(sAlo + off) = lp;
                    }
                }
            load_W(sWhi, sWlo, mat + l + 1, tid);
            __syncthreads();
        }
    }

    // ---- epilogue (fragment layout) ----
    if (mode == 1) {
#pragma unroll
        for (int rt = 0; rt < 2; rt++)
#pragma unroll
            for (int rr = 0; rr < 2; rr++) {
                int r = blockbase + w * 32 + rt * 16 + rr * 8 + gid;
                if (r < NN) {
#pragma unroll
                    for (int n = 0; n < 8; n++)
                        *(float2*)(g_t + r * 64 + n * 8 + 2 * tid4) =
                            make_float2(acc[rt][n][2 * rr], acc[rt][n][2 * rr + 1]);
                }
            }
        // BN stats on z (masked)
        float s[16], q[16];
#pragma unroll
        for (int n = 0; n < 8; n++)
#pragma unroll
            for (int h = 0; h < 2; h++) {
                float as = 0.f, aq = 0.f;
#pragma unroll
                for (int rt = 0; rt < 2; rt++)
#pragma unroll
                    for (int rr = 0; rr < 2; rr++) {
                        int r = blockbase + w * 32 + rt * 16 + rr * 8 + gid;
                        if (r < NN) {
                            float z = acc[rt][n][2 * rr + h];
                            as += z; aq += z * z;
                        }
                    }
                s[n * 2 + h] = as; q[n * 2 + h] = aq;
            }
#pragma unroll
        for (int idx = 0; idx < 16; idx++)
#pragma unroll
            for (int o = 4; o < 32; o <<= 1) {
                s[idx] += __shfl_xor_sync(0xffffffffu, s[idx], o);
                q[idx] += __shfl_xor_sync(0xffffffffu, q[idx], o);
            }
        __syncthreads();           // mma reads of sW done -> overlay
        sstats[tid] = 0.f;
        __syncthreads();
        if (gid == 0) {
#pragma unroll
            for (int n = 0; n < 8; n++)
#pragma unroll
                for (int h = 0; h < 2; h++) {
                    int col = n * 8 + 2 * tid4 + h;
                    atomicAdd(&sstats[col], s[n * 2 + h]);
                    atomicAdd(&sstats[64 + col], q[n * 2 + h]);
                }
        }
        __syncthreads();
        atomicAdd(&g_sums[slot * 128 + tid], sstats[tid]);
    } else {
        float* dst = (mode == 0) ? g_h : g_v;
#pragma unroll
        for (int rt = 0; rt < 2; rt++)
#pragma unroll
            for (int rr = 0; rr < 2; rr++) {
                int r = blockbase + w * 32 + rt * 16 + rr * 8 + gid;
                if (r < NN) {
#pragma unroll
                    for (int n = 0; n < 8; n++) {
                        float f0 = acc[rt][n][2 * rr], f1 = acc[rt][n][2 * rr + 1];
                        if (mode == 0) { f0 = fmaxf(f0, 0.f); f1 = fmaxf(f1, 0.f); }
                        *(float2*)(dst + r * 64 + n * 8 + 2 * tid4) = make_float2(f0, f1);
                        if (mode == 0)
                            *(float2*)(g_res + r * 64 + n * 8 + 2 * tid4) = make_float2(f0, f1);
                    }
                }
            }
    }
}

// ---------------- gather: t[n] = h[n] + sum_{src in N(n)} h[src] ----------
// 6250 blocks x 256 threads, 16 nodes/block, 16 lanes/node: high occupancy,
// ~100k independent tasks -> L2 latency hidden (this layout beat in-GEMM fusion).
__global__ void k_gather() {
    int n = blockIdx.x * 16 + (threadIdx.x >> 4);
    int lane = threadIdx.x & 15;
    const float4* h4 = (const float4*)g_h;
    float4 acc = h4[n * 16 + lane];
    int e = g_rowptr[n], e1 = g_rowptr[n + 1];
    for (; e + 1 < e1; e += 2) {
        int s0 = __ldg(&g_ssrc[e]), s1 = __ldg(&g_ssrc[e + 1]);
        float4 b0 = h4[s0 * 16 + lane];
        float4 b1 = h4[s1 * 16 + lane];
        acc.x += b0.x + b1.x; acc.y += b0.y + b1.y;
        acc.z += b0.z + b1.z; acc.w += b0.w + b1.w;
    }
    if (e < e1) {
        int s0 = __ldg(&g_ssrc[e]);
        float4 b0 = h4[s0 * 16 + lane];
        acc.x += b0.x; acc.y += b0.y; acc.z += b0.z; acc.w += b0.w;
    }
    ((float4*)g_t)[n * 16 + lane] = acc;
}

// ---------------- BN finalize + apply + relu (+ residual) --------------------
__global__ void k_apply(int addres, int slot,
                        const float* __restrict__ gamma,
                        const float* __restrict__ beta) {
    __shared__ float ssc[64], ssh[64];
    int tid = threadIdx.x;
    if (tid < 64) {
        float mean = g_sums[slot * 128 + tid] * (1.f / NN);
        float var = fmaxf(g_sums[slot * 128 + 64 + tid] * (1.f / NN) - mean * mean, 0.f);
        float sc = gamma[tid] * rsqrtf(var + EPSBN);
        ssc[tid] = sc;
        ssh[tid] = beta[tid] - mean * sc;
    }
    __syncthreads();
    int i = blockIdx.x * 256 + tid;   // float4 index, exactly NN*16
    int f4 = i & 15;
    float4 sc = ((const float4*)ssc)[f4];
    float4 sh = ((const float4*)ssh)[f4];
    float4 z = ((const float4*)g_t)[i];
    float4 v;
    v.x = fmaxf(z.x * sc.x + sh.x, 0.f);
    v.y = fmaxf(z.y * sc.y + sh.y, 0.f);
    v.z = fmaxf(z.z * sc.z + sh.z, 0.f);
    v.w = fmaxf(z.w * sc.w + sh.w, 0.f);
    if (addres) {
        float4 r = ((const float4*)g_res)[i];
        v.x += r.x; v.y += r.y; v.z += r.z; v.w += r.w;
        ((float4*)g_res)[i] = v;
    }
    ((float4*)g_h)[i] = v;
}

// ---------------- readout ----------------
__global__ void k_bounds(const int* __restrict__ batch) {
    int i = blockIdx.x * 256 + threadIdx.x;
    if (i >= NN) return;
    int b = batch[i];
    int bp = (i == 0) ? -1 : batch[i - 1];
    for (int g = bp + 1; g <= b; g++) g_gstart[g] = i;
    if (i == NN - 1) {
        for (int g = b + 1; g <= NG; g++) g_gstart[g] = NN;
    }
}

__global__ void __launch_bounds__(128) k_readout(const float* __restrict__ Wo,
                                                 const float* __restrict__ predW,
                                                 const float* __restrict__ predb,
                                                 float* __restrict__ out) {
    int g = blockIdx.x, tid = threadIdx.x;
    int s = g_gstart[g], e = g_gstart[g + 1];
    __shared__ float smw[4 * 68];
    __shared__ float red[68];
    __shared__ float pn[64];
    __shared__ float emb[64];
    __shared__ float wmx[4][4];
    const float4* sc4 = (const float4*)g_scores;

    float m[4] = {-1e30f, -1e30f, -1e30f, -1e30f};
    for (int n = s + tid; n < e; n += 128) {
        float4 v = sc4[n];
        m[0] = fmaxf(m[0], v.x); m[1] = fmaxf(m[1], v.y);
        m[2] = fmaxf(m[2], v.z); m[3] = fmaxf(m[3], v.w);
    }
#pragma unroll
    for (int h = 0; h < 4; h++)
#pragma unroll
        for (int d = 16; d; d >>= 1)
            m[h] = fmaxf(m[h], __shfl_xor_sync(0xffffffffu, m[h], d));
    if ((tid & 31) == 0)
#pragma unroll
        for (int h = 0; h < 4; h++) wmx[tid >> 5][h] = m[h];
    __syncthreads();
#pragma unroll
    for (int h = 0; h < 4; h++)
        m[h] = fmaxf(fmaxf(wmx[0][h], wmx[1][h]), fmaxf(wmx[2][h], wmx[3][h]));

    float pool[64];
    float sw[4] = {0.f, 0.f, 0.f, 0.f};
#pragma unroll
    for (int k = 0; k < 64; k++) pool[k] = 0.f;
    for (int n = s + tid; n < e; n += 128) {
        float4 v = sc4[n];
        float w[4] = {expf(v.x - m[0]), expf(v.y - m[1]),
                      expf(v.z - m[2]), expf(v.w - m[3])};
        sw[0] += w[0]; sw[1] += w[1]; sw[2] += w[2]; sw[3] += w[3];
        const float4* vv = (const float4*)(g_v + n * 64);
#pragma unroll
        for (int h = 0; h < 4; h++) {
#pragma unroll
            for (int i = 0; i < 4; i++) {
                float4 t = vv[h * 4 + i];
                pool[h * 16 + i * 4 + 0] += w[h] * t.x;
                pool[h * 16 + i * 4 + 1] += w[h] * t.y;
                pool[h * 16 + i * 4 + 2] += w[h] * t.z;
                pool[h * 16 + i * 4 + 3] += w[h] * t.w;
            }
        }
    }
#pragma unroll
    for (int k = 0; k < 64; k++)
#pragma unroll
        for (int d = 16; d; d >>= 1)
            pool[k] += __shfl_xor_sync(0xffffffffu, pool[k], d);
#pragma unroll
    for (int h = 0; h < 4; h++)
#pragma unroll
        for (int d = 16; d; d >>= 1)
            sw[h] += __shfl_xor_sync(0xffffffffu, sw[h], d);
    int wid = tid >> 5;
    if ((tid & 31) == 0) {
#pragma unroll
        for (int k = 0; k < 64; k++) smw[wid * 68 + k] = pool[k];
#pragma unroll
        for (int h = 0; h < 4; h++) smw[wid * 68 + 64 + h] = sw[h];
    }
    __syncthreads();
    if (tid < 68) red[tid] = smw[tid] + smw[68 + tid] + smw[136 + tid] + smw[204 + tid];
    __syncthreads();
    if (tid < 64) {
        float den = red[64 + (tid >> 4)];
        pn[tid] = (den > 0.f) ? red[tid] / den : 0.f;
    }
    __syncthreads();
    if (tid < 64) {
        float s2 = 0.f;
        for (int k = 0; k < 64; k++) s2 += pn[k] * Wo[k * 64 + tid];
        emb[tid] = s2;
        out[g * 64 + tid] = s2;
    }
    __syncthreads();
    {
        float s2 = predb[tid];
        for (int k = 0; k < 64; k++) s2 += emb[k] * predW[k * 128 + tid];
        out[NG * 64 + g * 128 + tid] = s2;
    }
}

// ---------------- launch ----------------
extern "C" void kernel_launch(void* const* d_in, const int* in_sizes, int n_in,
                              void* d_out, int out_size) {
    const float* x        = (const float*)d_in[0];
    const int*   ei       = (const int*)d_in[1];
    const int*   batch    = (const int*)d_in[2];
    const float* fn_gamma = (const float*)d_in[3];
    const float* fn_beta  = (const float*)d_in[4];
    const float* proj_W   = (const float*)d_in[5];
    const float* proj_b   = (const float*)d_in[6];
    const float* mlp_W    = (const float*)d_in[7];
    const float* mlp_b    = (const float*)d_in[8];
    const float* norm_g   = (const float*)d_in[9];
    const float* norm_b   = (const float*)d_in[10];
    const float* seed     = (const float*)d_in[11];
    const float* Wk       = (const float*)d_in[12];
    const float* Wv       = (const float*)d_in[13];
    const float* Wo       = (const float*)d_in[14];
    const float* predW    = (const float*)d_in[15];
    const float* predb    = (const float*)d_in[16];
    float* out = (float*)d_out;

    k_init<<<391, 256>>>();
    k_count<<<3907, 256>>>(ei);
    k_scan1<<<NBS, 256>>>();
    k_scan2<<<1, 128>>>();
    k_scan3<<<NBS, 256>>>();
    k_scatter<<<3907, 256>>>(ei);

    k_prepack<<<224, 256>>>(mlp_W, proj_W, Wv);
    k_bnstats<<<512, 256>>>(x);
    k_tc<<<GB, 128>>>(0, 1, x, 12, proj_b, 0, fn_gamma, fn_beta);   // BN+proj

    for (int m = 0; m < 4; m++) {
        for (int c = 0; c < 2; c++) {
            int slot = 1 + m * 2 + c;
            k_gather<<<6250, 256>>>();
            k_tc<<<GB, 128>>>(1, 3, nullptr, m * 3, mlp_b + m * 192, slot, nullptr, nullptr);
            k_apply<<<6250, 256>>>(c, slot, norm_g + m * 64, norm_b + m * 64);
        }
    }

    k_tc<<<GB, 128>>>(2, 1, nullptr, 13, nullptr, 0, Wk, seed);     // v + fused scores
    k_bounds<<<391, 256>>>(batch);
    k_readout<<<NG, 128>>>(Wo, predW, predb, out);
}